// round 11
// baseline (speedup 1.0000x reference)
#include <cuda_runtime.h>
#include <math.h>

#define S_  512
#define L_  128
#define D_  256
#define H2_ 128
#define P_  16
#define B_  128
#define F_  256
#define FEAT_ 640
#define ED_ 64
#define GRID_ 148
#define NT_ 512

typedef unsigned long long u64;

// Scratch (device globals — no allocations allowed)
__device__ float g_attwT[D_ * H2_];     // [d][h]
__device__ float g_condT[FEAT_ * F_];   // [k][f]
__device__ float g_featsT[FEAT_ * B_];  // [k][b]
__device__ float g_th[B_ * F_];         // [b][f]
__device__ unsigned g_bar;              // zero-init; monotonic across replays

__device__ __forceinline__ u64 pack2(float x, float y) {
    u64 r; asm("mov.b64 %0, {%1, %2};" : "=l"(r) : "f"(x), "f"(y)); return r;
}
__device__ __forceinline__ void unpack2(u64 v, float& x, float& y) {
    asm("mov.b64 {%0, %1}, %2;" : "=f"(x), "=f"(y) : "l"(v));
}
__device__ __forceinline__ void fma2(u64& d, u64 a, u64 b) {
    asm("fma.rn.f32x2 %0, %1, %2, %0;" : "+l"(d) : "l"(a), "l"(b));
}

__device__ __forceinline__ void grid_sync() {
    __syncthreads();
    if (threadIdx.x == 0) {
        __threadfence();
        unsigned ticket = atomicAdd(&g_bar, 1u);
        unsigned target = (ticket / GRID_ + 1u) * GRID_;
        volatile unsigned* p = &g_bar;
        while (*p < target) { }
        __threadfence();
    }
    __syncthreads();
}

__global__ __launch_bounds__(NT_, 1) void fused_all(
    const int* __restrict__ x,        // [S, L]
    const int* __restrict__ ents,     // [B, 2]
    const int* __restrict__ spos,     // [B, P, 2]
    const int* __restrict__ tpos,     // [B, P, 2]
    const float* __restrict__ emb,    // [V, D]
    const float* __restrict__ ent_emb,// [E_V, ED]
    const float* __restrict__ attw_W, // [H2, D]
    const float* __restrict__ attw_b, // [H2]
    const float* __restrict__ attw2_W,// [1, H2]
    const float* __restrict__ cond_W, // [F, FEAT]
    const float* __restrict__ cond_b, // [F]
    const float* __restrict__ lin_W,  // [2, F]
    const float* __restrict__ lin_b,  // [2]
    float* __restrict__ out)          // [B, 2]
{
    extern __shared__ float sm[];
    const int cta = blockIdx.x, tid = threadIdx.x;
    const int wi = tid >> 5, lane = tid & 31;

    __shared__ int   toks[32];
    __shared__ float part[32][17];
    __shared__ float logits[32];
    __shared__ float wgt[32];
    __shared__ u64   sp2[16][32];
    __shared__ float r0s[8], r1s[8];

    // ================= Phase 0: transposes (coalesced reads) =================
    {
        int gt = cta * NT_ + tid, gs = GRID_ * NT_;
        for (int i = gt; i < H2_ * D_; i += gs) {       // i = h*256 + d
            int h = i >> 8, d = i & 255;
            g_attwT[d * H2_ + h] = attw_W[i];
        }
        for (int i = gt; i < F_ * FEAT_; i += gs) {     // i = f*640 + k
            int f = i / FEAT_;
            int k = i - f * FEAT_;
            g_condT[k * F_ + f] = cond_W[i];
        }
    }
    grid_sync();

    // ================= Phase 1: pool (one b per CTA, both pools) =============
    float* ws = sm;                  // [256][128]  attwT
    float* Hm = sm + D_ * H2_;       // [32][257]   rows 0-15 s-pool, 16-31 t-pool

    // stage full attwT (128 KB), straight coalesced copy
    {
        const float4* src = reinterpret_cast<const float4*>(g_attwT);
        float4* dst = reinterpret_cast<float4*>(ws);
        #pragma unroll
        for (int j = 0; j < 16; j++) dst[tid + NT_ * j] = src[tid + NT_ * j];
    }

    const int b = cta;
    if (b < B_) {
        if (tid < 32) {
            int pool = tid >> 4, p = tid & 15;
            const int* pos = pool ? tpos : spos;
            int s = pos[(b * P_ + p) * 2 + 0];
            int l = pos[(b * P_ + p) * 2 + 1];
            toks[tid] = x[s * L_ + l];
        }
        __syncthreads();
        // gather 32 embedding rows (coalesced, 2 rows per pass)
        #pragma unroll
        for (int j = 0; j < 16; j++) {
            int i = tid + NT_ * j;          // 8192 items
            int r = i >> 8, d = i & 255;
            Hm[r * 257 + d] = emb[(size_t)toks[r] * D_ + d];
        }
        __syncthreads();

        // Phase B: row = lane (32 rows), cols = wi*8..wi*8+7 (16 warps)
        const int col0 = wi * 8;
        const float* wrow = ws + col0;
        const float* hrow = Hm + lane * 257;
        u64 a0 = 0ull, a1 = 0ull, a2 = 0ull, a3 = 0ull;
        #pragma unroll 8
        for (int d = 0; d < D_; d++) {
            float a = hrow[d];
            u64 ap = pack2(a, a);
            const ulonglong2* wq = reinterpret_cast<const ulonglong2*>(wrow + d * H2_);
            ulonglong2 q0 = wq[0], q1 = wq[1];
            fma2(a0, ap, q0.x); fma2(a1, ap, q0.y);
            fma2(a2, ap, q1.x); fma2(a3, ap, q1.y);
        }

        // tanh + attw2 weighting over this thread's 8 cols
        {
            float cs_ = 0.f, e0, e1;
            unpack2(a0, e0, e1);
            cs_ += tanhf(e0 + attw_b[col0+0]) * attw2_W[col0+0]
                 + tanhf(e1 + attw_b[col0+1]) * attw2_W[col0+1];
            unpack2(a1, e0, e1);
            cs_ += tanhf(e0 + attw_b[col0+2]) * attw2_W[col0+2]
                 + tanhf(e1 + attw_b[col0+3]) * attw2_W[col0+3];
            unpack2(a2, e0, e1);
            cs_ += tanhf(e0 + attw_b[col0+4]) * attw2_W[col0+4]
                 + tanhf(e1 + attw_b[col0+5]) * attw2_W[col0+5];
            unpack2(a3, e0, e1);
            cs_ += tanhf(e0 + attw_b[col0+6]) * attw2_W[col0+6]
                 + tanhf(e1 + attw_b[col0+7]) * attw2_W[col0+7];
            part[lane][wi] = cs_;
        }
        __syncthreads();
        if (tid < 32) {
            float s = 0.f;
            #pragma unroll
            for (int q = 0; q < 16; q++) s += part[tid][q];
            logits[tid] = s;
        }
        __syncthreads();
        if (tid < 2) {
            int base = tid * 16;
            float mx = logits[base];
            #pragma unroll
            for (int p2 = 1; p2 < 16; p2++) mx = fmaxf(mx, logits[base + p2]);
            float e[16]; float sum = 0.f;
            #pragma unroll
            for (int p2 = 0; p2 < 16; p2++) { e[p2] = __expf(logits[base + p2] - mx); sum += e[p2]; }
            float inv = 1.f / sum;
            #pragma unroll
            for (int p2 = 0; p2 < 16; p2++) wgt[base + p2] = e[p2] * inv;
        }
        __syncthreads();
        // weighted pools: tid<256 -> s-pool dim k, tid>=256 -> t-pool dim k
        {
            int pool = tid >> 8, k = tid & 255;
            const float* wp = wgt + pool * 16;
            const float* hp = Hm + pool * 16 * 257 + k;
            float v = 0.f;
            #pragma unroll
            for (int p2 = 0; p2 < 16; p2++) v += wp[p2] * hp[p2 * 257];
            g_featsT[(pool * D_ + k) * B_ + b] = v;
        }
        if (tid < 128) {
            int eidx = ents[b * 2 + (tid >> 6)];
            g_featsT[(2 * D_ + tid) * B_ + b] = ent_emb[(size_t)eidx * ED_ + (tid & 63)];
        }
    }
    grid_sync();

    // ================= Phase 2: gemm (128 tile-tasks, 8b x 32f) ==============
    if (cta < 128) {
        const int bt = cta >> 3, ft = cta & 7;
        const int b0 = bt * 8, f0 = ft * 32;
        float* fs  = sm;                 // [640][8]
        float* cst = sm + FEAT_ * 8;     // [640][33]

        #pragma unroll
        for (int j = 0; j < 10; j++) {
            int i = tid + NT_ * j;       // 5120 items: k=i>>3, bb=i&7
            fs[i] = g_featsT[(i >> 3) * B_ + b0 + (i & 7)];
        }
        #pragma unroll
        for (int j = 0; j < 40; j++) {   // 20480 items (coalesced read)
            int i = tid + NT_ * j;
            int k = i >> 5, f = i & 31;
            cst[k * 33 + f] = g_condT[k * F_ + f0 + f];
        }
        __syncthreads();

        const int pr = wi & 3, kq = wi >> 2;   // b-pair, K-quarter (160 each)
        const float* cb = cst + kq * 160 * 33 + lane;
        const float* fb = fs + kq * 160 * 8 + pr * 2;
        u64 acc = 0ull;
        #pragma unroll 8
        for (int kk = 0; kk < 160; kk++) {
            float w = cb[kk * 33];
            u64 fp = *reinterpret_cast<const u64*>(fb + kk * 8);
            fma2(acc, pack2(w, w), fp);
        }
        sp2[wi][lane] = acc;
        __syncthreads();
        if (wi < 4) {
            float x0, x1, y0, y1, z0, z1, w0, w1;
            unpack2(sp2[wi][lane],      x0, x1);
            unpack2(sp2[wi + 4][lane],  y0, y1);
            unpack2(sp2[wi + 8][lane],  z0, z1);
            unpack2(sp2[wi + 12][lane], w0, w1);
            float cbv = cond_b[f0 + lane];
            int bb = b0 + wi * 2;
            g_th[(bb + 0) * F_ + f0 + lane] = tanhf(((x0 + y0) + (z0 + w0)) + cbv);
            g_th[(bb + 1) * F_ + f0 + lane] = tanhf(((x1 + y1) + (z1 + w1)) + cbv);
        }
    }
    grid_sync();

    // ================= Phase 3: head ========================================
    if (cta < B_ && tid < F_) {
        float t  = g_th[cta * F_ + tid];
        float q0 = t * lin_W[tid];
        float q1 = t * lin_W[F_ + tid];
        #pragma unroll
        for (int off = 16; off; off >>= 1) {
            q0 += __shfl_xor_sync(0xffffffffu, q0, off);
            q1 += __shfl_xor_sync(0xffffffffu, q1, off);
        }
        if (lane == 0) { r0s[wi] = q0; r1s[wi] = q1; }
        __syncthreads();
        if (tid == 0) {
            float s0 = lin_b[0], s1 = lin_b[1];
            #pragma unroll
            for (int w = 0; w < 8; w++) { s0 += r0s[w]; s1 += r1s[w]; }
            out[cta * 2 + 0] = s0;
            out[cta * 2 + 1] = s1;
        }
    }
}

#define DYN_SMEM ((D_ * H2_ + 32 * 257) * 4)   /* 163,968 B (phase 1 is max) */

extern "C" void kernel_launch(void* const* d_in, const int* in_sizes, int n_in,
                              void* d_out, int out_size)
{
    const int*   x       = (const int*)  d_in[0];
    const int*   ents    = (const int*)  d_in[1];
    const int*   spos    = (const int*)  d_in[2];
    const int*   tpos    = (const int*)  d_in[3];
    const float* emb     = (const float*)d_in[4];
    const float* ent_emb = (const float*)d_in[5];
    const float* attw_W  = (const float*)d_in[6];
    const float* attw_b  = (const float*)d_in[7];
    const float* attw2_W = (const float*)d_in[8];
    const float* cond_W  = (const float*)d_in[9];
    const float* cond_b  = (const float*)d_in[10];
    const float* lin_W   = (const float*)d_in[11];
    const float* lin_b   = (const float*)d_in[12];
    float* out = (float*)d_out;

    cudaFuncSetAttribute(fused_all, cudaFuncAttributeMaxDynamicSharedMemorySize, DYN_SMEM);
    fused_all<<<GRID_, NT_, DYN_SMEM>>>(x, ents, spos, tpos, emb, ent_emb,
                                        attw_W, attw_b, attw2_W,
                                        cond_W, cond_b, lin_W, lin_b, out);
}